// round 2
// baseline (speedup 1.0000x reference)
#include <cuda_runtime.h>

#define D   128        // feature dim (in == out == 128)
#define KN  32         // neighbors per node
#define THREADS 128    // 4 warps = 1 node per block

__device__ float g_v[D];   // v = feat_weights @ attn_weights

// ---------------- prep: v[j] = sum_d W[j][d] * a[d] ----------------
__global__ void prep_kernel(const float* __restrict__ W,
                            const float* __restrict__ a) {
    int j = threadIdx.x;
    float s = 0.f;
#pragma unroll 8
    for (int d = 0; d < D; d++) s = fmaf(W[j * D + d], a[d], s);
    g_v[j] = s;
}

__device__ __forceinline__ float warpSum(float x) {
#pragma unroll
    for (int o = 16; o; o >>= 1) x += __shfl_xor_sync(0xffffffffu, x, o);
    return x;
}
__device__ __forceinline__ float warpMax(float x) {
#pragma unroll
    for (int o = 16; o; o >>= 1) x = fmaxf(x, __shfl_xor_sync(0xffffffffu, x, o));
    return x;
}

// --------- fused attention + aggregate + output GEMM, 4 warps/node ---------
__global__ void __launch_bounds__(THREADS, 5)
gat_kernel(const float* __restrict__ self_vecs,
           const float* __restrict__ neigh,
           const float* __restrict__ W,
           const float* __restrict__ bias,
           float* __restrict__ out) {
    __shared__ float  plog[4][KN];     // per-warp partial neighbor logits
    __shared__ float  sself[4];        // per-warp partial self logit
    __shared__ float  svec[D];         // aggregated vector (input space)
    __shared__ float4 gpart[4][D / 4]; // GEMM partials per j-split warp

    const int warp = threadIdx.x >> 5;
    const int lane = threadIdx.x & 31;
    const int d    = threadIdx.x;               // this thread's dim (0..127)
    const int node = blockIdx.x;

    const float vd = g_v[d];

    // self row: 1 float per thread, 128B coalesced per warp
    const float sv = __ldcs(self_vecs + (size_t)node * D + d);
    {
        const float p = warpSum(sv * vd);
        if (lane == 0) sself[warp] = p;
    }

    // stream all 32 neighbor rows: 1 float per thread per row
    const float* np = neigh + (size_t)node * KN * D + d;
    float r[KN];
#pragma unroll
    for (int k = 0; k < KN; k++) r[k] = __ldcs(np + k * D);

    // per-lane dot partials for this warp's 32 dims
    float a_[KN];
#pragma unroll
    for (int k = 0; k < KN; k++) a_[k] = r[k] * vd;

    // butterfly multi-reduce: lane l ends with quarter-dot for k==l
#pragma unroll
    for (int off = 16; off > 0; off >>= 1) {
        const bool hi = (lane & off);
#pragma unroll
        for (int i = 0; i < off; i++) {
            float mine = hi ? a_[i + off] : a_[i];
            float send = hi ? a_[i]       : a_[i + off];
            float recv = __shfl_xor_sync(0xffffffffu, send, off);
            a_[i] = mine + recv;
        }
    }
    plog[warp][lane] = a_[0];
    __syncthreads();

    // full logits (every warp redundantly; k == lane) + softmax
    float coef;
    {
        float x = plog[0][lane] + plog[1][lane] + plog[2][lane] + plog[3][lane]
                + (sself[0] + sself[1] + sself[2] + sself[3]);
        x = (x > 0.f) ? x : 0.2f * x;                 // leaky_relu(0.2)
        const float m   = warpMax(x);
        const float e   = __expf(x - m);
        const float inv = 1.0f / warpSum(e);
        coef = e * inv;
    }

    // weighted aggregate in INPUT space (self + sum_k coef_k * neigh_k)
    float acc = sv;
#pragma unroll
    for (int k = 0; k < KN; k++) {
        const float c = __shfl_sync(0xffffffffu, coef, k);
        acc = fmaf(c, r[k], acc);
    }
    svec[d] = acc;
    __syncthreads();

    // ---- output GEMM: out[d'] = relu(bias + sum_j svec[j] * W[j][d']) ----
    // warp `warp` handles j in [32*warp, 32*warp+32); lane owns 4 d' (float4)
    {
        float4 po = make_float4(0.f, 0.f, 0.f, 0.f);
        const float4* Wv = reinterpret_cast<const float4*>(W);
        const int jbase = warp * KN;
#pragma unroll 8
        for (int jj = 0; jj < KN; jj++) {
            const int j = jbase + jj;
            const float  sj = svec[j];
            const float4 wj = Wv[j * (D / 4) + lane];
            po.x = fmaf(sj, wj.x, po.x);
            po.y = fmaf(sj, wj.y, po.y);
            po.z = fmaf(sj, wj.z, po.z);
            po.w = fmaf(sj, wj.w, po.w);
        }
        gpart[warp][lane] = po;
    }
    __syncthreads();

    // final reduce: thread owns dim d
    {
        const float* gp = reinterpret_cast<const float*>(gpart);
        float t = gp[0 * D + d] + gp[1 * D + d] + gp[2 * D + d] + gp[3 * D + d];
        t += bias[d];
        out[(size_t)node * D + d] = fmaxf(t, 0.f);
    }
}

extern "C" void kernel_launch(void* const* d_in, const int* in_sizes, int n_in,
                              void* d_out, int out_size) {
    const float* self_vecs = (const float*)d_in[0];
    const float* neigh     = (const float*)d_in[1];
    const float* W         = (const float*)d_in[2];
    const float* attn      = (const float*)d_in[3];
    const float* bias      = (const float*)d_in[4];
    float* out = (float*)d_out;

    const int n = in_sizes[0] / D;

    prep_kernel<<<1, D>>>(W, attn);
    gat_kernel<<<n, THREADS>>>(self_vecs, neigh, W, bias, out);
}

// round 3
// speedup vs baseline: 1.1871x; 1.1871x over previous
#include <cuda_runtime.h>

#define D   128        // feature dim (in == out == 128)
#define KN  32         // neighbors per node
#define RPW 8          // neighbor rows per warp
#define THREADS 128    // 4 warps = 1 node per block

__device__ float g_v[D];   // v = feat_weights @ attn_weights

// ---------------- prep: v[j] = sum_d W[j][d] * a[d] ----------------
__global__ void prep_kernel(const float* __restrict__ W,
                            const float* __restrict__ a) {
    int j = threadIdx.x;
    float s = 0.f;
#pragma unroll 8
    for (int d = 0; d < D; d++) s = fmaf(W[j * D + d], a[d], s);
    g_v[j] = s;
}

__device__ __forceinline__ float warpSum(float x) {
#pragma unroll
    for (int o = 16; o; o >>= 1) x += __shfl_xor_sync(0xffffffffu, x, o);
    return x;
}
__device__ __forceinline__ float warpMax(float x) {
#pragma unroll
    for (int o = 16; o; o >>= 1) x = fmaxf(x, __shfl_xor_sync(0xffffffffu, x, o));
    return x;
}

// ------- fused attention + aggregate + output GEMM, row-split 4 warps ------
__global__ void __launch_bounds__(THREADS, 6)
gat_kernel(const float* __restrict__ self_vecs,
           const float* __restrict__ neigh,
           const float* __restrict__ W,
           const float* __restrict__ bias,
           float* __restrict__ out) {
    __shared__ float  plog[KN];        // full neighbor logits
    __shared__ float  sselflog;        // self logit
    __shared__ float4 gpart[4][D / 4]; // partials (aggregate, then GEMM)
    __shared__ float  svec[D];         // aggregated vector (input space)

    const int warp = threadIdx.x >> 5;
    const int lane = threadIdx.x & 31;
    const int node = blockIdx.x;

    const float4 v4 = reinterpret_cast<const float4*>(g_v)[lane];

    // ---- wide streaming loads: warp owns rows [8w, 8w+8), float4 per lane
    const float4* np = reinterpret_cast<const float4*>(
        neigh + (size_t)node * KN * D);
    float4 r[RPW];
#pragma unroll
    for (int i = 0; i < RPW; i++)
        r[i] = __ldcs(np + (warp * RPW + i) * (D / 4) + lane);

    float4 sv4 = make_float4(0.f, 0.f, 0.f, 0.f);
    if (warp == 0) {
        sv4 = __ldcs(reinterpret_cast<const float4*>(
                  self_vecs + (size_t)node * D) + lane);
        const float p = warpSum(
            fmaf(sv4.x, v4.x, fmaf(sv4.y, v4.y, fmaf(sv4.z, v4.z, sv4.w * v4.w))));
        if (lane == 0) sselflog = p;
    }

    // ---- per-lane dot partials for this warp's 8 rows
    float a_[RPW];
#pragma unroll
    for (int i = 0; i < RPW; i++)
        a_[i] = fmaf(r[i].x, v4.x,
                fmaf(r[i].y, v4.y,
                fmaf(r[i].z, v4.z, r[i].w * v4.w)));

    // ---- butterfly multi-reduce (offsets 4,2,1): lane l -> row (l&7) partial
#pragma unroll
    for (int off = 4; off > 0; off >>= 1) {
        const bool hi = (lane & off);
#pragma unroll
        for (int i = 0; i < off; i++) {
            float mine = hi ? a_[i + off] : a_[i];
            float send = hi ? a_[i]       : a_[i + off];
            a_[i] = mine + __shfl_xor_sync(0xffffffffu, send, off);
        }
    }
    // finish sum across remaining lane bits 3,4 (same row replicated)
    float dot = a_[0];
    dot += __shfl_xor_sync(0xffffffffu, dot, 8);
    dot += __shfl_xor_sync(0xffffffffu, dot, 16);
    if (lane < RPW) plog[warp * RPW + lane] = dot;
    __syncthreads();

    // ---- softmax over 32 logits (redundant per warp; k == lane)
    float coef;
    {
        float x = plog[lane] + sselflog;
        x = (x > 0.f) ? x : 0.2f * x;                 // leaky_relu(0.2)
        const float m   = warpMax(x);
        const float e   = __expf(x - m);
        coef = e / warpSum(e);
    }

    // ---- partial aggregate over this warp's 8 rows (full 128 dims)
    float4 acc = sv4;                                  // self added by warp 0
#pragma unroll
    for (int i = 0; i < RPW; i++) {
        const float c = __shfl_sync(0xffffffffu, coef, warp * RPW + i);
        acc.x = fmaf(c, r[i].x, acc.x);
        acc.y = fmaf(c, r[i].y, acc.y);
        acc.z = fmaf(c, r[i].z, acc.z);
        acc.w = fmaf(c, r[i].w, acc.w);
    }
    gpart[warp][lane] = acc;
    __syncthreads();

    // ---- svec[d] = sum of 4 warp partials
    {
        const float* gf = reinterpret_cast<const float*>(gpart);
        const int tid = threadIdx.x;
        svec[tid] = (gf[0 * D + tid] + gf[1 * D + tid])
                  + (gf[2 * D + tid] + gf[3 * D + tid]);
    }
    __syncthreads();

    // ---- output GEMM: warp w handles j in [32w, 32w+32)
    {
        float4 po = make_float4(0.f, 0.f, 0.f, 0.f);
        const float4* Wv = reinterpret_cast<const float4*>(W);
        const int jbase = warp * 32;
#pragma unroll 8
        for (int jj = 0; jj < 32; jj++) {
            const int j = jbase + jj;
            const float  sj = svec[j];
            const float4 wj = Wv[j * (D / 4) + lane];
            po.x = fmaf(sj, wj.x, po.x);
            po.y = fmaf(sj, wj.y, po.y);
            po.z = fmaf(sj, wj.z, po.z);
            po.w = fmaf(sj, wj.w, po.w);
        }
        gpart[warp][lane] = po;   // safe: all svec reads fenced by sync above
    }
    __syncthreads();

    // ---- final reduce + bias + relu
    {
        const float* gf = reinterpret_cast<const float*>(gpart);
        const int tid = threadIdx.x;
        float t = (gf[0 * D + tid] + gf[1 * D + tid])
                + (gf[2 * D + tid] + gf[3 * D + tid]) + bias[tid];
        out[(size_t)node * D + tid] = fmaxf(t, 0.f);
    }
}

extern "C" void kernel_launch(void* const* d_in, const int* in_sizes, int n_in,
                              void* d_out, int out_size) {
    const float* self_vecs = (const float*)d_in[0];
    const float* neigh     = (const float*)d_in[1];
    const float* W         = (const float*)d_in[2];
    const float* attn      = (const float*)d_in[3];
    const float* bias      = (const float*)d_in[4];
    float* out = (float*)d_out;

    const int n = in_sizes[0] / D;

    prep_kernel<<<1, D>>>(W, attn);
    gat_kernel<<<n, THREADS>>>(self_vecs, neigh, W, bias, out);
}

// round 4
// speedup vs baseline: 1.1879x; 1.0007x over previous
#include <cuda_runtime.h>

#define D   128        // feature dim (in == out == 128)
#define KN  32         // neighbors per node
#define RPW 8          // neighbor rows per warp (attention phase)
#define NPB 4          // nodes per block
#define THREADS 512    // 16 warps: 4 per node

__device__ float g_v[D];   // v = feat_weights @ attn_weights

// ---------------- prep: v[j] = sum_d W[j][d] * a[d] ----------------
__global__ void prep_kernel(const float* __restrict__ W,
                            const float* __restrict__ a) {
    int j = threadIdx.x;
    float s = 0.f;
#pragma unroll 8
    for (int d = 0; d < D; d++) s = fmaf(W[j * D + d], a[d], s);
    g_v[j] = s;
}

__device__ __forceinline__ float warpSum(float x) {
#pragma unroll
    for (int o = 16; o; o >>= 1) x += __shfl_xor_sync(0xffffffffu, x, o);
    return x;
}
__device__ __forceinline__ float warpMax(float x) {
#pragma unroll
    for (int o = 16; o; o >>= 1) x = fmaxf(x, __shfl_xor_sync(0xffffffffu, x, o));
    return x;
}

// ---- fused attention + aggregate + W-amortized output GEMM, 4 nodes/block --
__global__ void __launch_bounds__(THREADS, 2)
gat_kernel(const float* __restrict__ self_vecs,
           const float* __restrict__ neigh,
           const float* __restrict__ W,
           const float* __restrict__ bias,
           float* __restrict__ out,
           int n_nodes) {
    __shared__ float  plog[NPB][KN];       // neighbor logits per node slot
    __shared__ float  sselflog[NPB];       // self logit per node slot
    __shared__ float  svec[NPB][D];        // aggregated vectors (input space)
    __shared__ float4 gp[16][NPB][D / 4];  // GEMM partials [warp][node][dim/4]
                                           // (agg phase aliases gp[w][0][*])

    const int warp  = threadIdx.x >> 5;    // 0..15
    const int lane  = threadIdx.x & 31;
    const int nslot = warp >> 2;           // node slot 0..3
    const int nwarp = warp & 3;            // warp within node 0..3
    const int node  = blockIdx.x * NPB + nslot;
    const int nodec = (node < n_nodes) ? node : (n_nodes - 1);   // clamped

    const float4 v4 = reinterpret_cast<const float4*>(g_v)[lane];

    // ---- wide streaming loads: warp owns rows [8*nwarp, 8*nwarp+8)
    const float4* np = reinterpret_cast<const float4*>(
        neigh + (size_t)nodec * KN * D);
    float4 r[RPW];
#pragma unroll
    for (int i = 0; i < RPW; i++)
        r[i] = __ldcs(np + (nwarp * RPW + i) * (D / 4) + lane);

    float4 sv4 = make_float4(0.f, 0.f, 0.f, 0.f);
    if (nwarp == 0) {
        sv4 = __ldcs(reinterpret_cast<const float4*>(
                  self_vecs + (size_t)nodec * D) + lane);
        const float p = warpSum(
            fmaf(sv4.x, v4.x, fmaf(sv4.y, v4.y, fmaf(sv4.z, v4.z, sv4.w * v4.w))));
        if (lane == 0) sselflog[nslot] = p;
    }

    // ---- per-lane dot partials for this warp's 8 rows
    float a_[RPW];
#pragma unroll
    for (int i = 0; i < RPW; i++)
        a_[i] = fmaf(r[i].x, v4.x,
                fmaf(r[i].y, v4.y,
                fmaf(r[i].z, v4.z, r[i].w * v4.w)));

    // ---- butterfly multi-reduce (offsets 4,2,1): lane l -> row (l&7)
#pragma unroll
    for (int off = 4; off > 0; off >>= 1) {
        const bool hi = (lane & off);
#pragma unroll
        for (int i = 0; i < off; i++) {
            float mine = hi ? a_[i + off] : a_[i];
            float send = hi ? a_[i]       : a_[i + off];
            a_[i] = mine + __shfl_xor_sync(0xffffffffu, send, off);
        }
    }
    float dot = a_[0];
    dot += __shfl_xor_sync(0xffffffffu, dot, 8);
    dot += __shfl_xor_sync(0xffffffffu, dot, 16);
    if (lane < RPW) plog[nslot][nwarp * RPW + lane] = dot;
    __syncthreads();

    // ---- softmax over 32 logits (redundant per warp; k == lane)
    float coef;
    {
        float x = plog[nslot][lane] + sselflog[nslot];
        x = (x > 0.f) ? x : 0.2f * x;                 // leaky_relu(0.2)
        const float m = warpMax(x);
        const float e = __expf(x - m);
        coef = e / warpSum(e);
    }

    // ---- partial aggregate over this warp's 8 rows (full 128 dims)
    float4 acc = sv4;                                 // self added by nwarp 0
#pragma unroll
    for (int i = 0; i < RPW; i++) {
        const float c = __shfl_sync(0xffffffffu, coef, nwarp * RPW + i);
        acc.x = fmaf(c, r[i].x, acc.x);
        acc.y = fmaf(c, r[i].y, acc.y);
        acc.z = fmaf(c, r[i].z, acc.z);
        acc.w = fmaf(c, r[i].w, acc.w);
    }
    gp[warp][0][lane] = acc;                          // alias as agg partial
    __syncthreads();

    // ---- svec[ns][d] = sum of that node's 4 warp partials
    {
        const int ns  = threadIdx.x >> 7;             // 0..3
        const int dim = threadIdx.x & (D - 1);
        const float* gf = reinterpret_cast<const float*>(gp);
        const size_t stride = NPB * D;                // floats per gp[w]
        svec[ns][dim] = (gf[(ns * 4 + 0) * stride + dim]
                       + gf[(ns * 4 + 1) * stride + dim])
                      + (gf[(ns * 4 + 2) * stride + dim]
                       + gf[(ns * 4 + 3) * stride + dim]);
    }
    __syncthreads();

    // ---- output GEMM: warp w owns j in [8w, 8w+8), ALL 4 nodes share wj
    {
        float4 po[NPB];
#pragma unroll
        for (int ns = 0; ns < NPB; ns++) po[ns] = make_float4(0.f, 0.f, 0.f, 0.f);

        const float4* Wv = reinterpret_cast<const float4*>(W);
        const int jbase = warp * 8;
#pragma unroll
        for (int jj = 0; jj < 8; jj++) {
            const int j = jbase + jj;
            const float4 wj = Wv[j * (D / 4) + lane];
#pragma unroll
            for (int ns = 0; ns < NPB; ns++) {
                const float sj = svec[ns][j];
                po[ns].x = fmaf(sj, wj.x, po[ns].x);
                po[ns].y = fmaf(sj, wj.y, po[ns].y);
                po[ns].z = fmaf(sj, wj.z, po[ns].z);
                po[ns].w = fmaf(sj, wj.w, po[ns].w);
            }
        }
#pragma unroll
        for (int ns = 0; ns < NPB; ns++) gp[warp][ns][lane] = po[ns];
    }
    __syncthreads();

    // ---- final 16-way reduce + bias + relu; thread owns (node slot, dim)
    {
        const int ns  = threadIdx.x >> 7;
        const int dim = threadIdx.x & (D - 1);
        const int node2 = blockIdx.x * NPB + ns;
        const float* gf = reinterpret_cast<const float*>(gp);
        const size_t stride = NPB * D;
        float t = 0.f;
#pragma unroll
        for (int w = 0; w < 16; w++)
            t += gf[w * stride + ns * D + dim];
        t += bias[dim];
        if (node2 < n_nodes)
            out[(size_t)node2 * D + dim] = fmaxf(t, 0.f);
    }
}

extern "C" void kernel_launch(void* const* d_in, const int* in_sizes, int n_in,
                              void* d_out, int out_size) {
    const float* self_vecs = (const float*)d_in[0];
    const float* neigh     = (const float*)d_in[1];
    const float* W         = (const float*)d_in[2];
    const float* attn      = (const float*)d_in[3];
    const float* bias      = (const float*)d_in[4];
    float* out = (float*)d_out;

    const int n = in_sizes[0] / D;

    prep_kernel<<<1, D>>>(W, attn);
    const int blocks = (n + NPB - 1) / NPB;
    gat_kernel<<<blocks, THREADS>>>(self_vecs, neigh, W, bias, out, n);
}